// round 6
// baseline (speedup 1.0000x reference)
#include <cuda_runtime.h>
#include <math.h>

// ---------------------------------------------------------------------------
// ArticulatoryVQTokenizer fused kernel (fp32 + f32x2 packed FMA, sm_100a).
// Paired-token VQ with pair-interleaved codebook operand; per-warp H slab
// with double-buffered VQ chunks; zB stashed to global to avoid spills.
// Outputs (float32): [0,1835008) recon | [1835008,1966080) indices |
//   [1966080] commit_loss | [1966081] perplexity
// ---------------------------------------------------------------------------

#define TPB        256
#define NWARP      8
#define NTOK       131072
#define NTASK2     2048              // tasks of 64 tokens (2 per lane)
#define GRID_A     148
#define KCODES     512
#define LATENT     64
#define HID        128
#define INDIM      14

#define OUT_IDX_OFF   1835008
#define OUT_COMMIT    1966080
#define OUT_PERP      1966081

// smem layout (float offsets)
#define OFF_W1P   0                      // 2048
#define OFF_W2    2048                   // 8192
#define OFF_DW1P  10240                  // 8192
#define OFF_DW2T  18432                  // 2048
#define OFF_EB1   20480                  // 128
#define OFF_LN1G  20608
#define OFF_LN1B  20736
#define OFF_B2    20864                  // 64
#define OFF_DB1   20928
#define OFF_LN2G  21056
#define OFF_LN2B  21184
#define OFF_DB2   21312                  // 16
#define OFF_CC    21328                  // 512
#define OFF_HIST  21840                  // 512 ints
#define OFF_SLAB  22352                  // 8 warps * 4096 floats (16KB each)
#define SLAB_F    4096
#define SMEM_FLOATS (OFF_SLAB + NWARP * SLAB_F)   // 55120
#define SMEM_BYTES  (SMEM_FLOATS * 4)             // 220480

typedef unsigned long long u64;

__device__ int          g_counts[KCODES];
__device__ float        g_taskc[NTASK2];
__device__ unsigned int g_ticket = 0;
__device__ unsigned int g_done = 0;
__device__ __align__(16) float g_cbi[KCODES * LATENT];       // pair-interleaved
__device__ __align__(16) float g_zstash[GRID_A * NWARP * 2048];

__device__ __forceinline__ u64 pk2(float lo, float hi) {
    u64 r; asm("mov.b64 %0, {%1, %2};" : "=l"(r) : "f"(lo), "f"(hi)); return r;
}
__device__ __forceinline__ void up2(u64 v, float& lo, float& hi) {
    asm("mov.b64 {%0, %1}, %2;" : "=f"(lo), "=f"(hi) : "l"(v));
}
__device__ __forceinline__ u64 f2fma(u64 a, u64 b, u64 c) {
    u64 d; asm("fma.rn.f32x2 %0, %1, %2, %3;" : "=l"(d) : "l"(a), "l"(b), "l"(c));
    return d;
}

// gelu exact, matching jax: 0.5 * x * (1 + erf(x / sqrt(2)))
__device__ __forceinline__ float gelu_exact(float t) {
    float u = __fdiv_rn(t, 1.41421356237309515f);
    float e = erff(u);
    return __fmul_rn(__fmul_rn(0.5f, t), __fadd_rn(1.0f, e));
}

// ---------------------------------------------------------------------------
// prep: pair-interleave codebook: g_cbi[(c>>1)*128 + 2k + (c&1)] = cb[c*64+k]
__global__ void vq_prep_kernel(const float* __restrict__ cb) {
    int idx = blockIdx.x * blockDim.x + threadIdx.x;   // 64*512 = 32768
    int c = idx >> 6, k = idx & 63;
    g_cbi[(c >> 1) * 128 + 2 * k + (c & 1)] = cb[idx];
}

// ---------------------------------------------------------------------------
// Encoder for one token -> z[64]. Slab H at slab[j*32+lane]. Bit-exact order.
__device__ __forceinline__ void encode_token(
    const float* __restrict__ sm, float* __restrict__ slab, int lane,
    const float* __restrict__ X, int tok, float* z)
{
    const float inv128 = 0.0078125f;
    float xr[INDIM];
    const float* xp = X + (size_t)tok * INDIM;
#pragma unroll
    for (int i = 0; i < INDIM; i++) xr[i] = __ldg(xp + i);
    u64 xd[INDIM];
#pragma unroll
    for (int i = 0; i < INDIM; i++) xd[i] = pk2(xr[i], xr[i]);

    // pass 1: h1 = x @ W1 + b1; sum
    float sum = 0.f;
#pragma unroll 2
    for (int g = 0; g < 32; g++) {
        const ulonglong2* w0 = (const ulonglong2*)(sm + OFF_W1P + (2 * g) * 32);
        const ulonglong2* w1 = (const ulonglong2*)(sm + OFF_W1P + (2 * g + 1) * 32);
        u64 a0 = 0ull, a1 = 0ull;
#pragma unroll
        for (int ii = 0; ii < 7; ii++) {
            ulonglong2 u0 = w0[ii], u1 = w1[ii];
            a0 = f2fma(xd[2 * ii], u0.x, a0);
            a0 = f2fma(xd[2 * ii + 1], u0.y, a0);
            a1 = f2fma(xd[2 * ii], u1.x, a1);
            a1 = f2fma(xd[2 * ii + 1], u1.y, a1);
        }
        float h0, h1, h2, h3;
        up2(a0, h0, h1); up2(a1, h2, h3);
        h0 = __fadd_rn(h0, sm[OFF_EB1 + 4 * g + 0]);
        h1 = __fadd_rn(h1, sm[OFF_EB1 + 4 * g + 1]);
        h2 = __fadd_rn(h2, sm[OFF_EB1 + 4 * g + 2]);
        h3 = __fadd_rn(h3, sm[OFF_EB1 + 4 * g + 3]);
        sum = __fadd_rn(__fadd_rn(__fadd_rn(__fadd_rn(sum, h0), h1), h2), h3);
        slab[(4 * g + 0) * 32 + lane] = h0;
        slab[(4 * g + 1) * 32 + lane] = h1;
        slab[(4 * g + 2) * 32 + lane] = h2;
        slab[(4 * g + 3) * 32 + lane] = h3;
    }
    float mu = __fmul_rn(sum, inv128);
    // pass 2: variance
    float vs = 0.f;
#pragma unroll 4
    for (int j = 0; j < HID; j++) {
        float d = __fsub_rn(slab[j * 32 + lane], mu);
        vs = __fadd_rn(vs, __fmul_rn(d, d));
    }
    float var = __fmul_rn(vs, inv128);
    float rs = __fdiv_rn(1.0f, sqrtf(__fadd_rn(var, 1e-5f)));
    // pass 3: g = gelu(LN(h)) in place (independent chains -> ILP)
#pragma unroll 4
    for (int j = 0; j < HID; j++) {
        float h = slab[j * 32 + lane];
        float t = __fadd_rn(__fmul_rn(__fmul_rn(__fsub_rn(h, mu), rs), sm[OFF_LN1G + j]), sm[OFF_LN1B + j]);
        slab[j * 32 + lane] = gelu_exact(t);
    }
    // pass 4: z = g @ W2 + b2  (j-sequential chains per z-lane)
    u64 zp[32];
#pragma unroll
    for (int t2 = 0; t2 < 32; t2++) zp[t2] = 0ull;
#pragma unroll 2
    for (int j = 0; j < HID; j++) {
        float gj = slab[j * 32 + lane];
        u64 ag = pk2(gj, gj);
        const ulonglong2* wv = (const ulonglong2*)(sm + OFF_W2 + j * LATENT);
#pragma unroll
        for (int t2 = 0; t2 < 16; t2++) {
            ulonglong2 u = wv[t2];
            zp[2 * t2]     = f2fma(ag, u.x, zp[2 * t2]);
            zp[2 * t2 + 1] = f2fma(ag, u.y, zp[2 * t2 + 1]);
        }
    }
#pragma unroll
    for (int t2 = 0; t2 < 32; t2++) up2(zp[t2], z[2 * t2], z[2 * t2 + 1]);
#pragma unroll
    for (int k = 0; k < LATENT; k++) z[k] = __fadd_rn(z[k], sm[OFF_B2 + k]);
}

// ---------------------------------------------------------------------------
// Decoder for one token from z[64]; returns commit partial. Bit-exact order.
__device__ __forceinline__ float decode_token(
    const float* __restrict__ sm, float* __restrict__ slab, int lane,
    const float* __restrict__ CB, int tok, int bidx,
    const float* z, float* __restrict__ out)
{
    const float inv128 = 0.0078125f;
    float qst[LATENT];
    float closs = 0.f;
    const float4* qp = (const float4*)(CB + (size_t)bidx * LATENT);
#pragma unroll
    for (int k4 = 0; k4 < 16; k4++) {
        float4 f = __ldg(qp + k4);
        float qv[4] = {f.x, f.y, f.z, f.w};
#pragma unroll
        for (int u = 0; u < 4; u++) {
            int k = 4 * k4 + u;
            float dqz = __fsub_rn(qv[u], z[k]);
            closs = __fadd_rn(closs, __fmul_rn(dqz, dqz));
            qst[k] = __fadd_rn(z[k], dqz);
        }
    }

    // dec1: h2 = q_st @ dW1 + db1, 8 j per group (q-pk2 reused across 4 pairs)
    float sum = 0.f;
#pragma unroll 1
    for (int G = 0; G < 16; G++) {
        const ulonglong2* w0 = (const ulonglong2*)(sm + OFF_DW1P + (4 * G + 0) * 128);
        const ulonglong2* w1 = (const ulonglong2*)(sm + OFF_DW1P + (4 * G + 1) * 128);
        const ulonglong2* w2 = (const ulonglong2*)(sm + OFF_DW1P + (4 * G + 2) * 128);
        const ulonglong2* w3 = (const ulonglong2*)(sm + OFF_DW1P + (4 * G + 3) * 128);
        u64 a0 = 0ull, a1 = 0ull, a2 = 0ull, a3 = 0ull;
#pragma unroll
        for (int kk = 0; kk < 32; kk++) {
            u64 q0 = pk2(qst[2 * kk], qst[2 * kk]);
            u64 q1 = pk2(qst[2 * kk + 1], qst[2 * kk + 1]);
            ulonglong2 u0 = w0[kk], u1 = w1[kk], u2 = w2[kk], u3 = w3[kk];
            a0 = f2fma(q0, u0.x, a0); a0 = f2fma(q1, u0.y, a0);
            a1 = f2fma(q0, u1.x, a1); a1 = f2fma(q1, u1.y, a1);
            a2 = f2fma(q0, u2.x, a2); a2 = f2fma(q1, u2.y, a2);
            a3 = f2fma(q0, u3.x, a3); a3 = f2fma(q1, u3.y, a3);
        }
        float h[8];
        up2(a0, h[0], h[1]); up2(a1, h[2], h[3]);
        up2(a2, h[4], h[5]); up2(a3, h[6], h[7]);
#pragma unroll
        for (int i = 0; i < 8; i++) {
            float hv = __fadd_rn(h[i], sm[OFF_DB1 + 8 * G + i]);
            sum = __fadd_rn(sum, hv);
            slab[(8 * G + i) * 32 + lane] = hv;
        }
    }
    float mu2 = __fmul_rn(sum, inv128);
    float vs2 = 0.f;
#pragma unroll 4
    for (int j = 0; j < HID; j++) {
        float d = __fsub_rn(slab[j * 32 + lane], mu2);
        vs2 = __fadd_rn(vs2, __fmul_rn(d, d));
    }
    float var2 = __fmul_rn(vs2, inv128);
    float rs2 = __fdiv_rn(1.0f, sqrtf(__fadd_rn(var2, 1e-5f)));
    // gelu pass in place
#pragma unroll 4
    for (int j = 0; j < HID; j++) {
        float h = slab[j * 32 + lane];
        float t = __fadd_rn(__fmul_rn(__fmul_rn(__fsub_rn(h, mu2), rs2), sm[OFF_LN2G + j]), sm[OFF_LN2B + j]);
        slab[j * 32 + lane] = gelu_exact(t);
    }
    // dec2 dot
    u64 op[7];
#pragma unroll
    for (int i = 0; i < 7; i++) op[i] = 0ull;
#pragma unroll 2
    for (int j = 0; j < HID; j++) {
        float gj = slab[j * 32 + lane];
        u64 ag = pk2(gj, gj);
        const ulonglong2* rv = (const ulonglong2*)(sm + OFF_DW2T + j * 16);
        ulonglong2 u0 = rv[0], u1 = rv[1], u2 = rv[2], u3 = rv[3];
        op[0] = f2fma(ag, u0.x, op[0]);
        op[1] = f2fma(ag, u0.y, op[1]);
        op[2] = f2fma(ag, u1.x, op[2]);
        op[3] = f2fma(ag, u1.y, op[3]);
        op[4] = f2fma(ag, u2.x, op[4]);
        op[5] = f2fma(ag, u2.y, op[5]);
        op[6] = f2fma(ag, u3.x, op[6]);
    }
    float o[14];
#pragma unroll
    for (int i = 0; i < 7; i++) up2(op[i], o[2 * i], o[2 * i + 1]);
    float* opo = out + (size_t)tok * INDIM;
#pragma unroll
    for (int i = 0; i < INDIM; i++) opo[i] = __fadd_rn(o[i], sm[OFF_DB2 + i]);
    return closs;
}

// ---------------------------------------------------------------------------
__global__ void __launch_bounds__(TPB, 1)
vq_fused_kernel(const float* __restrict__ X,
                const float* __restrict__ EW1, const float* __restrict__ EB1,
                const float* __restrict__ L1G, const float* __restrict__ L1B,
                const float* __restrict__ EW2, const float* __restrict__ EB2,
                const float* __restrict__ CB,
                const float* __restrict__ DW1, const float* __restrict__ DB1,
                const float* __restrict__ L2G, const float* __restrict__ L2B,
                const float* __restrict__ DW2, const float* __restrict__ DB2,
                float* __restrict__ out) {
    extern __shared__ float sm[];
    int* sHist = (int*)(sm + OFF_HIST);

    const int tid  = threadIdx.x;
    const int wid  = tid >> 5;
    const int lane = tid & 31;
    const int wgid = blockIdx.x * NWARP + wid;
    float* slab = sm + OFF_SLAB + wid * SLAB_F;

    // ---- one-time block init ----
    for (int idx = tid; idx < 64 * 32; idx += TPB) {   // enc_w1 pair-interleave
        int p = idx >> 5, r = idx & 31, i = r >> 1, s = r & 1;
        sm[OFF_W1P + idx] = (i < INDIM) ? EW1[i * HID + 2 * p + s] : 0.f;
    }
    for (int i = tid; i < HID * LATENT; i += TPB) sm[OFF_W2 + i] = EW2[i];
    for (int idx = tid; idx < 64 * 128; idx += TPB) {  // dec_w1 pair-interleave
        int p = idx >> 7, r = idx & 127, k = r >> 1, s = r & 1;
        sm[OFF_DW1P + idx] = DW1[k * HID + 2 * p + s];
    }
    for (int i = tid; i < HID * INDIM; i += TPB) {     // dec_w2 [j][i16]
        int r = i / INDIM, c = i % INDIM;
        sm[OFF_DW2T + r * 16 + c] = DW2[i];
    }
    for (int i = tid; i < HID; i += TPB) { sm[OFF_DW2T + i * 16 + 14] = 0.f; sm[OFF_DW2T + i * 16 + 15] = 0.f; }
    for (int i = tid; i < HID; i += TPB) {
        sm[OFF_EB1 + i] = EB1[i]; sm[OFF_LN1G + i] = L1G[i]; sm[OFF_LN1B + i] = L1B[i];
        sm[OFF_DB1 + i] = DB1[i]; sm[OFF_LN2G + i] = L2G[i]; sm[OFF_LN2B + i] = L2B[i];
    }
    for (int i = tid; i < LATENT; i += TPB) sm[OFF_B2 + i] = EB2[i];
    for (int i = tid; i < 16; i += TPB) sm[OFF_DB2 + i] = (i < INDIM) ? DB2[i] : 0.f;
    for (int i = tid; i < KCODES; i += TPB) sHist[i] = 0;
    // cc = ||c||^2, sequential square-then-add
    for (int c = tid; c < KCODES; c += TPB) {
        const float* p = CB + c * LATENT;
        float acc = 0.f;
#pragma unroll
        for (int k = 0; k < LATENT; k++) {
            float v = __ldg(p + k);
            acc = __fadd_rn(acc, __fmul_rn(v, v));
        }
        sm[OFF_CC + c] = acc;
    }
    __syncthreads();

    const float4* CBI4 = (const float4*)g_cbi;
    float4* zstash = (float4*)(g_zstash + (size_t)wgid * 2048);

    // ---- dynamic ticket loop: task = 64 tokens (2 per lane) ----
    for (;;) {
        unsigned int t;
        if (lane == 0) t = atomicAdd(&g_ticket, 1u);
        t = __shfl_sync(0xffffffffu, t, 0);
        if (t >= NTASK2) break;
        const int tokA = (int)t * 64 + lane;
        const int tokB = tokA + 32;

        float zA[LATENT];
        encode_token(sm, slab, lane, X, tokA, zA);
        float zzA = 0.f;
#pragma unroll
        for (int k = 0; k < LATENT; k++) zzA = __fadd_rn(zzA, __fmul_rn(zA[k], zA[k]));

        float zB[LATENT];
        encode_token(sm, slab, lane, X, tokB, zB);
        float zzB = 0.f;
#pragma unroll
        for (int k = 0; k < LATENT; k++) zzB = __fadd_rn(zzB, __fmul_rn(zB[k], zB[k]));

        // stash zB (read back after decodeA; frees regs during decodeA)
#pragma unroll
        for (int k4 = 0; k4 < 16; k4++) {
            float4 f;
            f.x = zB[4 * k4]; f.y = zB[4 * k4 + 1];
            f.z = zB[4 * k4 + 2]; f.w = zB[4 * k4 + 3];
            zstash[k4 * 32 + lane] = f;
        }

        // ---- VQ: 64 chunks of 8 codes (4 interleaved pairs), double-buffered
        float bestA = 3.4e38f, bestB = 3.4e38f;
        int bidxA = 0, bidxB = 0;
        {
            float4* buf[2] = { (float4*)slab, (float4*)(slab + 512) };
            float4 p0 = CBI4[lane], p1 = CBI4[32 + lane];
            float4 p2 = CBI4[64 + lane], p3 = CBI4[96 + lane];
            buf[0][lane] = p0; buf[0][32 + lane] = p1;
            buf[0][64 + lane] = p2; buf[0][96 + lane] = p3;
            __syncwarp();
#pragma unroll 1
            for (int ch = 0; ch < 64; ch++) {
                const float* cur = (const float*)buf[ch & 1];
                if (ch < 63) {
                    const float4* s2 = CBI4 + (ch + 1) * 128;
                    p0 = s2[lane]; p1 = s2[32 + lane];
                    p2 = s2[64 + lane]; p3 = s2[96 + lane];
                }
                u64 aA[4] = {0ull, 0ull, 0ull, 0ull};
                u64 aB[4] = {0ull, 0ull, 0ull, 0ull};
#pragma unroll
                for (int kk = 0; kk < 16; kk++) {
                    u64 zdA0 = pk2(zA[4 * kk + 0], zA[4 * kk + 0]);
                    u64 zdA1 = pk2(zA[4 * kk + 1], zA[4 * kk + 1]);
                    u64 zdA2 = pk2(zA[4 * kk + 2], zA[4 * kk + 2]);
                    u64 zdA3 = pk2(zA[4 * kk + 3], zA[4 * kk + 3]);
                    u64 zdB0 = pk2(zB[4 * kk + 0], zB[4 * kk + 0]);
                    u64 zdB1 = pk2(zB[4 * kk + 1], zB[4 * kk + 1]);
                    u64 zdB2 = pk2(zB[4 * kk + 2], zB[4 * kk + 2]);
                    u64 zdB3 = pk2(zB[4 * kk + 3], zB[4 * kk + 3]);
#pragma unroll
                    for (int p = 0; p < 4; p++) {
                        const ulonglong2* bp = (const ulonglong2*)(cur + p * 128 + 8 * kk);
                        ulonglong2 u = bp[0], v = bp[1];
                        aA[p] = f2fma(zdA0, u.x, aA[p]);
                        aA[p] = f2fma(zdA1, u.y, aA[p]);
                        aA[p] = f2fma(zdA2, v.x, aA[p]);
                        aA[p] = f2fma(zdA3, v.y, aA[p]);
                        aB[p] = f2fma(zdB0, u.x, aB[p]);
                        aB[p] = f2fma(zdB1, u.y, aB[p]);
                        aB[p] = f2fma(zdB2, v.x, aB[p]);
                        aB[p] = f2fma(zdB3, v.y, aB[p]);
                    }
                }
#pragma unroll
                for (int p = 0; p < 4; p++) {
                    float dA0, dA1, dB0, dB1;
                    up2(aA[p], dA0, dA1);
                    up2(aB[p], dB0, dB1);
                    int c0 = ch * 8 + 2 * p;
                    float cc0 = sm[OFF_CC + c0], cc1 = sm[OFF_CC + c0 + 1];
                    float eA0 = __fadd_rn(__fsub_rn(zzA, __fmul_rn(2.0f, dA0)), cc0);
                    float eA1 = __fadd_rn(__fsub_rn(zzA, __fmul_rn(2.0f, dA1)), cc1);
                    float eB0 = __fadd_rn(__fsub_rn(zzB, __fmul_rn(2.0f, dB0)), cc0);
                    float eB1 = __fadd_rn(__fsub_rn(zzB, __fmul_rn(2.0f, dB1)), cc1);
                    if (eA0 < bestA) { bestA = eA0; bidxA = c0; }
                    if (eA1 < bestA) { bestA = eA1; bidxA = c0 + 1; }
                    if (eB0 < bestB) { bestB = eB0; bidxB = c0; }
                    if (eB1 < bestB) { bestB = eB1; bidxB = c0 + 1; }
                }
                if (ch < 63) {
                    float4* nb = buf[(ch + 1) & 1];
                    nb[lane] = p0; nb[32 + lane] = p1;
                    nb[64 + lane] = p2; nb[96 + lane] = p3;
                }
                __syncwarp();
            }
        }
        atomicAdd(&sHist[bidxA], 1);
        atomicAdd(&sHist[bidxB], 1);
        out[OUT_IDX_OFF + tokA] = (float)bidxA;
        out[OUT_IDX_OFF + tokB] = (float)bidxB;

        float clA = decode_token(sm, slab, lane, CB, tokA, bidxA, zA, out);

        // reload zB from stash (same thread wrote it -> program-order visible)
        float zBr[LATENT];
#pragma unroll
        for (int k4 = 0; k4 < 16; k4++) {
            float4 f = zstash[k4 * 32 + lane];
            zBr[4 * k4] = f.x; zBr[4 * k4 + 1] = f.y;
            zBr[4 * k4 + 2] = f.z; zBr[4 * k4 + 3] = f.w;
        }
        float clB = decode_token(sm, slab, lane, CB, tokB, bidxB, zBr, out);

        // per-task deterministic commit partial (fixed shfl tree)
        float cl = __fadd_rn(clA, clB);
#pragma unroll
        for (int s = 16; s > 0; s >>= 1)
            cl = __fadd_rn(cl, __shfl_down_sync(0xffffffffu, cl, s));
        if (lane == 0) g_taskc[t] = cl;
    }

    // ---- merge histogram ----
    __syncthreads();
    for (int i = tid; i < KCODES; i += TPB) {
        int c = sHist[i];
        if (c) atomicAdd(&g_counts[i], c);
    }

    // ---- last-block finalize ----
    __threadfence();
    __shared__ unsigned int sTicket;
    if (tid == 0) sTicket = atomicAdd(&g_done, 1u);
    __syncthreads();
    if (sTicket == GRID_A - 1) {
        float* sRed = sm + OFF_SLAB;
        float s8 = 0.f;
#pragma unroll
        for (int j = 0; j < 8; j++) s8 += g_taskc[tid * 8 + j];
        float p0 = (float)g_counts[tid] * (1.0f / (float)NTOK);
        float p1 = (float)g_counts[tid + 256] * (1.0f / (float)NTOK);
        float ent = p0 * logf(p0 + 1e-10f) + p1 * logf(p1 + 1e-10f);
        sRed[tid] = s8;
        sRed[256 + tid] = ent;
        __syncthreads();
#pragma unroll
        for (int s = 128; s > 0; s >>= 1) {
            if (tid < s) {
                sRed[tid] += sRed[tid + s];
                sRed[256 + tid] += sRed[256 + tid + s];
            }
            __syncthreads();
        }
        if (tid == 0) {
            out[OUT_COMMIT] = 0.25f * (sRed[0] / ((float)NTOK * (float)LATENT));
            out[OUT_PERP] = expf(-sRed[256]);
        }
        __syncthreads();
        for (int i = tid; i < KCODES; i += TPB) g_counts[i] = 0;
        if (tid == 0) { g_done = 0; g_ticket = 0; }
    }
}

// ---------------------------------------------------------------------------
extern "C" void kernel_launch(void* const* d_in, const int* in_sizes, int n_in,
                              void* d_out, int out_size) {
    const float* x    = (const float*)d_in[0];
    const float* ew1  = (const float*)d_in[1];
    const float* eb1  = (const float*)d_in[2];
    const float* l1g  = (const float*)d_in[3];
    const float* l1b  = (const float*)d_in[4];
    const float* ew2  = (const float*)d_in[5];
    const float* eb2  = (const float*)d_in[6];
    const float* cb   = (const float*)d_in[7];
    const float* dw1  = (const float*)d_in[8];
    const float* db1  = (const float*)d_in[9];
    const float* l2g  = (const float*)d_in[10];
    const float* l2b  = (const float*)d_in[11];
    const float* dw2  = (const float*)d_in[12];
    const float* db2  = (const float*)d_in[13];
    float* out = (float*)d_out;

    cudaFuncSetAttribute(vq_fused_kernel,
                         cudaFuncAttributeMaxDynamicSharedMemorySize, SMEM_BYTES);

    vq_prep_kernel<<<64, 512>>>(cb);
    vq_fused_kernel<<<GRID_A, TPB, SMEM_BYTES>>>(
        x, ew1, eb1, l1g, l1b, ew2, eb2, cb,
        dw1, db1, l2g, l2b, dw2, db2, out);
}

// round 7
// speedup vs baseline: 1.2177x; 1.2177x over previous
#include <cuda_runtime.h>
#include <math.h>

// ---------------------------------------------------------------------------
// ArticulatoryVQTokenizer fused kernel (fp32 + f32x2 packed FMA, sm_100a).
// R5 structure + (a) zB global stash to kill decode-phase spills,
// (b) pair-interleaved codebook operand in VQ (fewer pk2 MOVs).
// Outputs (float32): [0,1835008) recon | [1835008,1966080) indices |
//   [1966080] commit_loss | [1966081] perplexity
// ---------------------------------------------------------------------------

#define TPB        256
#define NWARP      8
#define NTOK       131072
#define NTASK2     2048              // tasks of 64 tokens (2 per lane)
#define GRID_A     148
#define KCODES     512
#define LATENT     64
#define HID        128
#define INDIM      14

#define OUT_IDX_OFF   1835008
#define OUT_COMMIT    1966080
#define OUT_PERP      1966081

// smem layout (float offsets) — identical to R5
#define OFF_W1P   0                      // 2048
#define OFF_W2    2048                   // 8192
#define OFF_DW1P  10240                  // 8192
#define OFF_DW2T  18432                  // 2048
#define OFF_EB1   20480                  // 128
#define OFF_LN1G  20608
#define OFF_LN1B  20736
#define OFF_B2    20864                  // 64
#define OFF_DB1   20928
#define OFF_LN2G  21056
#define OFF_LN2B  21184
#define OFF_DB2   21312                  // 16
#define OFF_CC    21328                  // 512
#define OFF_HIST  21840                  // 512 ints
#define OFF_CHUNK 22352                  // 8 warps * 256 floats
#define OFF_H     24400                  // 128*256 thread-major
#define SMEM_FLOATS (OFF_H + HID * TPB)  // 57168
#define SMEM_BYTES  (SMEM_FLOATS * 4)    // 228672

typedef unsigned long long u64;

__device__ int          g_counts[KCODES];
__device__ float        g_taskc[NTASK2];
__device__ unsigned int g_ticket = 0;
__device__ unsigned int g_done = 0;
__device__ __align__(16) float g_cbi[KCODES * LATENT];          // pair-interleaved
__device__ __align__(16) float g_zstash[GRID_A * NWARP * 2048]; // per-warp zB stash

__device__ __forceinline__ u64 pk2(float lo, float hi) {
    u64 r; asm("mov.b64 %0, {%1, %2};" : "=l"(r) : "f"(lo), "f"(hi)); return r;
}
__device__ __forceinline__ void up2(u64 v, float& lo, float& hi) {
    asm("mov.b64 {%0, %1}, %2;" : "=f"(lo), "=f"(hi) : "l"(v));
}
__device__ __forceinline__ u64 f2fma(u64 a, u64 b, u64 c) {
    u64 d; asm("fma.rn.f32x2 %0, %1, %2, %3;" : "=l"(d) : "l"(a), "l"(b), "l"(c));
    return d;
}

// gelu exact, matching jax: 0.5 * x * (1 + erf(x / sqrt(2)))
__device__ __forceinline__ float gelu_exact(float t) {
    float u = __fdiv_rn(t, 1.41421356237309515f);
    float e = erff(u);
    return __fmul_rn(__fmul_rn(0.5f, t), __fadd_rn(1.0f, e));
}

// ---------------------------------------------------------------------------
// prep: pair-interleave codebook: g_cbi[(c>>1)*128 + 2k + (c&1)] = cb[c*64+k]
__global__ void vq_prep_kernel(const float* __restrict__ cb) {
    int idx = blockIdx.x * blockDim.x + threadIdx.x;   // 64*512 = 32768
    int c = idx >> 6, k = idx & 63;
    g_cbi[(c >> 1) * 128 + 2 * k + (c & 1)] = cb[idx];
}

// ---------------------------------------------------------------------------
// Encoder for one token: z[64] out. Identical to R5.
__device__ __forceinline__ void encode_token(
    float* sm, int tid, const float* __restrict__ X, int tok, float* z)
{
    const float inv128 = 0.0078125f;
    float xr[INDIM];
    const float* xp = X + (size_t)tok * INDIM;
#pragma unroll
    for (int i = 0; i < INDIM; i++) xr[i] = __ldg(xp + i);
    u64 xd[INDIM];
#pragma unroll
    for (int i = 0; i < INDIM; i++) xd[i] = pk2(xr[i], xr[i]);

    float sum = 0.f;
#pragma unroll 2
    for (int g = 0; g < 32; g++) {
        const ulonglong2* w0 = (const ulonglong2*)(sm + OFF_W1P + (2 * g) * 32);
        const ulonglong2* w1 = (const ulonglong2*)(sm + OFF_W1P + (2 * g + 1) * 32);
        u64 a0 = 0ull, a1 = 0ull;
#pragma unroll
        for (int ii = 0; ii < 7; ii++) {
            ulonglong2 u0 = w0[ii], u1 = w1[ii];
            a0 = f2fma(xd[2 * ii], u0.x, a0);
            a0 = f2fma(xd[2 * ii + 1], u0.y, a0);
            a1 = f2fma(xd[2 * ii], u1.x, a1);
            a1 = f2fma(xd[2 * ii + 1], u1.y, a1);
        }
        float h0, h1, h2, h3;
        up2(a0, h0, h1); up2(a1, h2, h3);
        h0 = __fadd_rn(h0, sm[OFF_EB1 + 4 * g + 0]);
        h1 = __fadd_rn(h1, sm[OFF_EB1 + 4 * g + 1]);
        h2 = __fadd_rn(h2, sm[OFF_EB1 + 4 * g + 2]);
        h3 = __fadd_rn(h3, sm[OFF_EB1 + 4 * g + 3]);
        sum = __fadd_rn(__fadd_rn(__fadd_rn(__fadd_rn(sum, h0), h1), h2), h3);
        sm[OFF_H + (4 * g + 0) * TPB + tid] = h0;
        sm[OFF_H + (4 * g + 1) * TPB + tid] = h1;
        sm[OFF_H + (4 * g + 2) * TPB + tid] = h2;
        sm[OFF_H + (4 * g + 3) * TPB + tid] = h3;
    }
    float mu = __fmul_rn(sum, inv128);
    float vs = 0.f;
#pragma unroll 4
    for (int j = 0; j < HID; j++) {
        float d = __fsub_rn(sm[OFF_H + j * TPB + tid], mu);
        vs = __fadd_rn(vs, __fmul_rn(d, d));
    }
    float var = __fmul_rn(vs, inv128);
    float rs = __fdiv_rn(1.0f, sqrtf(__fadd_rn(var, 1e-5f)));

    u64 zp[32];
#pragma unroll
    for (int t2 = 0; t2 < 32; t2++) zp[t2] = 0ull;
#pragma unroll 2
    for (int j = 0; j < HID; j++) {
        float h = sm[OFF_H + j * TPB + tid];
        float t = __fadd_rn(__fmul_rn(__fmul_rn(__fsub_rn(h, mu), rs), sm[OFF_LN1G + j]), sm[OFF_LN1B + j]);
        float gel = gelu_exact(t);
        u64 ag = pk2(gel, gel);
        const ulonglong2* wv = (const ulonglong2*)(sm + OFF_W2 + j * LATENT);
#pragma unroll
        for (int t2 = 0; t2 < 16; t2++) {
            ulonglong2 u = wv[t2];
            zp[2 * t2]     = f2fma(ag, u.x, zp[2 * t2]);
            zp[2 * t2 + 1] = f2fma(ag, u.y, zp[2 * t2 + 1]);
        }
    }
#pragma unroll
    for (int t2 = 0; t2 < 32; t2++) up2(zp[t2], z[2 * t2], z[2 * t2 + 1]);
#pragma unroll
    for (int k = 0; k < LATENT; k++) z[k] = __fadd_rn(z[k], sm[OFF_B2 + k]);
}

// ---------------------------------------------------------------------------
// Decoder for one token from z[64]; returns commit partial. R5 arithmetic.
__device__ __forceinline__ float decode_token(
    float* sm, int tid, const float* __restrict__ CB, int tok, int bidx,
    const float* z, float* __restrict__ out)
{
    const float inv128 = 0.0078125f;
    float qst[LATENT];
    float closs = 0.f;
    const float4* qp = (const float4*)(CB + (size_t)bidx * LATENT);
#pragma unroll
    for (int k4 = 0; k4 < 16; k4++) {
        float4 f = __ldg(qp + k4);
        float qv[4] = {f.x, f.y, f.z, f.w};
#pragma unroll
        for (int u = 0; u < 4; u++) {
            int k = 4 * k4 + u;
            float dqz = __fsub_rn(qv[u], z[k]);
            closs = __fadd_rn(closs, __fmul_rn(dqz, dqz));
            qst[k] = __fadd_rn(z[k], dqz);
        }
    }

    float sum = 0.f;
#pragma unroll 1
    for (int g = 0; g < 32; g++) {
        const ulonglong2* w0 = (const ulonglong2*)(sm + OFF_DW1P + (2 * g) * 128);
        const ulonglong2* w1 = (const ulonglong2*)(sm + OFF_DW1P + (2 * g + 1) * 128);
        u64 a0 = 0ull, a1 = 0ull;
#pragma unroll
        for (int kk = 0; kk < 32; kk++) {
            ulonglong2 u0 = w0[kk], u1 = w1[kk];
            u64 q0 = pk2(qst[2 * kk], qst[2 * kk]);
            u64 q1 = pk2(qst[2 * kk + 1], qst[2 * kk + 1]);
            a0 = f2fma(q0, u0.x, a0);
            a0 = f2fma(q1, u0.y, a0);
            a1 = f2fma(q0, u1.x, a1);
            a1 = f2fma(q1, u1.y, a1);
        }
        float h0, h1, h2, h3;
        up2(a0, h0, h1); up2(a1, h2, h3);
        h0 = __fadd_rn(h0, sm[OFF_DB1 + 4 * g + 0]);
        h1 = __fadd_rn(h1, sm[OFF_DB1 + 4 * g + 1]);
        h2 = __fadd_rn(h2, sm[OFF_DB1 + 4 * g + 2]);
        h3 = __fadd_rn(h3, sm[OFF_DB1 + 4 * g + 3]);
        sum = __fadd_rn(__fadd_rn(__fadd_rn(__fadd_rn(sum, h0), h1), h2), h3);
        sm[OFF_H + (4 * g + 0) * TPB + tid] = h0;
        sm[OFF_H + (4 * g + 1) * TPB + tid] = h1;
        sm[OFF_H + (4 * g + 2) * TPB + tid] = h2;
        sm[OFF_H + (4 * g + 3) * TPB + tid] = h3;
    }
    float mu2 = __fmul_rn(sum, inv128);
    float vs2 = 0.f;
#pragma unroll 4
    for (int j = 0; j < HID; j++) {
        float d = __fsub_rn(sm[OFF_H + j * TPB + tid], mu2);
        vs2 = __fadd_rn(vs2, __fmul_rn(d, d));
    }
    float var2 = __fmul_rn(vs2, inv128);
    float rs2 = __fdiv_rn(1.0f, sqrtf(__fadd_rn(var2, 1e-5f)));

    u64 op[7];
#pragma unroll
    for (int i = 0; i < 7; i++) op[i] = 0ull;
#pragma unroll 2
    for (int j = 0; j < HID; j++) {
        float h = sm[OFF_H + j * TPB + tid];
        float t = __fadd_rn(__fmul_rn(__fmul_rn(__fsub_rn(h, mu2), rs2), sm[OFF_LN2G + j]), sm[OFF_LN2B + j]);
        float gel = gelu_exact(t);
        u64 ag = pk2(gel, gel);
        const ulonglong2* rv = (const ulonglong2*)(sm + OFF_DW2T + j * 16);
        ulonglong2 u0 = rv[0], u1 = rv[1], u2 = rv[2], u3 = rv[3];
        op[0] = f2fma(ag, u0.x, op[0]);
        op[1] = f2fma(ag, u0.y, op[1]);
        op[2] = f2fma(ag, u1.x, op[2]);
        op[3] = f2fma(ag, u1.y, op[3]);
        op[4] = f2fma(ag, u2.x, op[4]);
        op[5] = f2fma(ag, u2.y, op[5]);
        op[6] = f2fma(ag, u3.x, op[6]);
    }
    float o[14];
#pragma unroll
    for (int i = 0; i < 7; i++) up2(op[i], o[2 * i], o[2 * i + 1]);
    float* opo = out + (size_t)tok * INDIM;
#pragma unroll
    for (int i = 0; i < INDIM; i++) opo[i] = __fadd_rn(o[i], sm[OFF_DB2 + i]);
    return closs;
}

// ---------------------------------------------------------------------------
__global__ void __launch_bounds__(TPB, 1)
vq_fused_kernel(const float* __restrict__ X,
                const float* __restrict__ EW1, const float* __restrict__ EB1,
                const float* __restrict__ L1G, const float* __restrict__ L1B,
                const float* __restrict__ EW2, const float* __restrict__ EB2,
                const float* __restrict__ CB,
                const float* __restrict__ DW1, const float* __restrict__ DB1,
                const float* __restrict__ L2G, const float* __restrict__ L2B,
                const float* __restrict__ DW2, const float* __restrict__ DB2,
                float* __restrict__ out) {
    extern __shared__ float sm[];
    int* sHist = (int*)(sm + OFF_HIST);

    const int tid  = threadIdx.x;
    const int wid  = tid >> 5;
    const int lane = tid & 31;
    const int wgid = blockIdx.x * NWARP + wid;

    // ---- one-time block init (identical to R5) ----
    for (int idx = tid; idx < 64 * 32; idx += TPB) {
        int p = idx >> 5, r = idx & 31, i = r >> 1, s = r & 1;
        sm[OFF_W1P + idx] = (i < INDIM) ? EW1[i * HID + 2 * p + s] : 0.f;
    }
    for (int i = tid; i < HID * LATENT; i += TPB) sm[OFF_W2 + i] = EW2[i];
    for (int idx = tid; idx < 64 * 128; idx += TPB) {
        int p = idx >> 7, r = idx & 127, k = r >> 1, s = r & 1;
        sm[OFF_DW1P + idx] = DW1[k * HID + 2 * p + s];
    }
    for (int i = tid; i < HID * INDIM; i += TPB) {
        int r = i / INDIM, c = i % INDIM;
        sm[OFF_DW2T + r * 16 + c] = DW2[i];
    }
    for (int i = tid; i < HID; i += TPB) { sm[OFF_DW2T + i * 16 + 14] = 0.f; sm[OFF_DW2T + i * 16 + 15] = 0.f; }
    for (int i = tid; i < HID; i += TPB) {
        sm[OFF_EB1 + i] = EB1[i]; sm[OFF_LN1G + i] = L1G[i]; sm[OFF_LN1B + i] = L1B[i];
        sm[OFF_DB1 + i] = DB1[i]; sm[OFF_LN2G + i] = L2G[i]; sm[OFF_LN2B + i] = L2B[i];
    }
    for (int i = tid; i < LATENT; i += TPB) sm[OFF_B2 + i] = EB2[i];
    for (int i = tid; i < 16; i += TPB) sm[OFF_DB2 + i] = (i < INDIM) ? DB2[i] : 0.f;
    for (int i = tid; i < KCODES; i += TPB) sHist[i] = 0;
    for (int c = tid; c < KCODES; c += TPB) {
        const float* p = CB + c * LATENT;
        float acc = 0.f;
#pragma unroll
        for (int k = 0; k < LATENT; k++) {
            float v = __ldg(p + k);
            acc = __fadd_rn(acc, __fmul_rn(v, v));
        }
        sm[OFF_CC + c] = acc;
    }
    __syncthreads();

    const float4* CBI4 = (const float4*)g_cbi;
    float4* myCh4 = (float4*)(sm + OFF_CHUNK + (size_t)wid * 256);
    const float* myCh = sm + OFF_CHUNK + (size_t)wid * 256;
    float4* zstash = (float4*)(g_zstash + (size_t)wgid * 2048);

    // ---- dynamic ticket loop: task = 64 tokens (paired lanes) ----
    for (;;) {
        unsigned int t;
        if (lane == 0) t = atomicAdd(&g_ticket, 1u);
        t = __shfl_sync(0xffffffffu, t, 0);
        if (t >= NTASK2) break;
        const int tokA = (int)t * 64 + lane;
        const int tokB = tokA + 32;

        float zA[LATENT];
        encode_token(sm, tid, X, tokA, zA);
        float zzA = 0.f;
#pragma unroll
        for (int k = 0; k < LATENT; k++) zzA = __fadd_rn(zzA, __fmul_rn(zA[k], zA[k]));

        float zB[LATENT];
        encode_token(sm, tid, X, tokB, zB);
        float zzB = 0.f;
#pragma unroll
        for (int k = 0; k < LATENT; k++) zzB = __fadd_rn(zzB, __fmul_rn(zB[k], zB[k]));

        // ---- paired VQ over 128 chunks of 4 codes (2 interleaved pairs) ----
        // myCh holds g_cbi chunk: pair p at myCh+p*128, element 2k+(c&1).
        float bestA = 3.4e38f, bestB = 3.4e38f;
        int bidxA = 0, bidxB = 0;
        {
            float4 pfa = CBI4[lane * 2 + 0];
            float4 pfb = CBI4[lane * 2 + 1];
            myCh4[lane * 2 + 0] = pfa;
            myCh4[lane * 2 + 1] = pfb;
            __syncwarp();
#pragma unroll 1
            for (int ch = 0; ch < 128; ch++) {
                if (ch + 1 < 128) {
                    pfa = CBI4[(ch + 1) * 64 + lane * 2 + 0];
                    pfb = CBI4[(ch + 1) * 64 + lane * 2 + 1];
                }
                const ulonglong2* b0 = (const ulonglong2*)(myCh);
                const ulonglong2* b1 = (const ulonglong2*)(myCh + 128);
                u64 aA0 = 0ull, aB0 = 0ull, aA1 = 0ull, aB1 = 0ull;
#pragma unroll
                for (int kk = 0; kk < 32; kk++) {
                    ulonglong2 u0 = b0[kk];
                    ulonglong2 u1 = b1[kk];
                    u64 zdA0 = pk2(zA[2 * kk],     zA[2 * kk]);
                    u64 zdA1 = pk2(zA[2 * kk + 1], zA[2 * kk + 1]);
                    u64 zdB0 = pk2(zB[2 * kk],     zB[2 * kk]);
                    u64 zdB1 = pk2(zB[2 * kk + 1], zB[2 * kk + 1]);
                    aA0 = f2fma(zdA0, u0.x, aA0);
                    aA0 = f2fma(zdA1, u0.y, aA0);
                    aB0 = f2fma(zdB0, u0.x, aB0);
                    aB0 = f2fma(zdB1, u0.y, aB0);
                    aA1 = f2fma(zdA0, u1.x, aA1);
                    aA1 = f2fma(zdA1, u1.y, aA1);
                    aB1 = f2fma(zdB0, u1.x, aB1);
                    aB1 = f2fma(zdB1, u1.y, aB1);
                }
                // pair0 = codes 4ch, 4ch+1 (lo, hi); pair1 = 4ch+2, 4ch+3
                float dA0, dA1, dA2, dA3, dB0, dB1, dB2, dB3;
                up2(aA0, dA0, dA1); up2(aA1, dA2, dA3);
                up2(aB0, dB0, dB1); up2(aB1, dB2, dB3);
                float cc0 = sm[OFF_CC + ch * 4 + 0];
                float cc1 = sm[OFF_CC + ch * 4 + 1];
                float cc2 = sm[OFF_CC + ch * 4 + 2];
                float cc3 = sm[OFF_CC + ch * 4 + 3];
                float eA0 = __fadd_rn(__fsub_rn(zzA, __fmul_rn(2.0f, dA0)), cc0);
                float eA1 = __fadd_rn(__fsub_rn(zzA, __fmul_rn(2.0f, dA1)), cc1);
                float eA2 = __fadd_rn(__fsub_rn(zzA, __fmul_rn(2.0f, dA2)), cc2);
                float eA3 = __fadd_rn(__fsub_rn(zzA, __fmul_rn(2.0f, dA3)), cc3);
                float eB0 = __fadd_rn(__fsub_rn(zzB, __fmul_rn(2.0f, dB0)), cc0);
                float eB1 = __fadd_rn(__fsub_rn(zzB, __fmul_rn(2.0f, dB1)), cc1);
                float eB2 = __fadd_rn(__fsub_rn(zzB, __fmul_rn(2.0f, dB2)), cc2);
                float eB3 = __fadd_rn(__fsub_rn(zzB, __fmul_rn(2.0f, dB3)), cc3);
                if (eA0 < bestA) { bestA = eA0; bidxA = ch * 4 + 0; }
                if (eA1 < bestA) { bestA = eA1; bidxA = ch * 4 + 1; }
                if (eA2 < bestA) { bestA = eA2; bidxA = ch * 4 + 2; }
                if (eA3 < bestA) { bestA = eA3; bidxA = ch * 4 + 3; }
                if (eB0 < bestB) { bestB = eB0; bidxB = ch * 4 + 0; }
                if (eB1 < bestB) { bestB = eB1; bidxB = ch * 4 + 1; }
                if (eB2 < bestB) { bestB = eB2; bidxB = ch * 4 + 2; }
                if (eB3 < bestB) { bestB = eB3; bidxB = ch * 4 + 3; }
                __syncwarp();
                if (ch + 1 < 128) {
                    myCh4[lane * 2 + 0] = pfa;
                    myCh4[lane * 2 + 1] = pfb;
                }
                __syncwarp();
            }
        }
        atomicAdd(&sHist[bidxA], 1);
        atomicAdd(&sHist[bidxB], 1);
        out[OUT_IDX_OFF + tokA] = (float)bidxA;
        out[OUT_IDX_OFF + tokB] = (float)bidxB;

        // stash zB so it is NOT live across decodeA (kills spills)
#pragma unroll
        for (int k4 = 0; k4 < 16; k4++) {
            float4 f;
            f.x = zB[4 * k4]; f.y = zB[4 * k4 + 1];
            f.z = zB[4 * k4 + 2]; f.w = zB[4 * k4 + 3];
            zstash[k4 * 32 + lane] = f;
        }

        float clA = decode_token(sm, tid, CB, tokA, bidxA, zA, out);

        float zBr[LATENT];
#pragma unroll
        for (int k4 = 0; k4 < 16; k4++) {
            float4 f = zstash[k4 * 32 + lane];
            zBr[4 * k4] = f.x; zBr[4 * k4 + 1] = f.y;
            zBr[4 * k4 + 2] = f.z; zBr[4 * k4 + 3] = f.w;
        }
        float clB = decode_token(sm, tid, CB, tokB, bidxB, zBr, out);

        // per-task deterministic commit partial (fixed shfl tree)
        float cl = __fadd_rn(clA, clB);
#pragma unroll
        for (int s = 16; s > 0; s >>= 1)
            cl = __fadd_rn(cl, __shfl_down_sync(0xffffffffu, cl, s));
        if (lane == 0) g_taskc[t] = cl;
    }

    // ---- merge histogram ----
    __syncthreads();
    for (int i = tid; i < KCODES; i += TPB) {
        int c = sHist[i];
        if (c) atomicAdd(&g_counts[i], c);
    }

    // ---- last-block finalize ----
    __threadfence();
    __shared__ unsigned int sTicket;
    if (tid == 0) sTicket = atomicAdd(&g_done, 1u);
    __syncthreads();
    if (sTicket == GRID_A - 1) {
        float* sRed = sm + OFF_CHUNK;
        float s8 = 0.f;
#pragma unroll
        for (int j = 0; j < 8; j++) s8 += g_taskc[tid * 8 + j];
        float p0 = (float)g_counts[tid] * (1.0f / (float)NTOK);
        float p1 = (float)g_counts[tid + 256] * (1.0f / (float)NTOK);
        float ent = p0 * logf(p0 + 1e-10f) + p1 * logf(p1 + 1e-10f);
        sRed[tid] = s8;
        sRed[256 + tid] = ent;
        __syncthreads();
#pragma unroll
        for (int s = 128; s > 0; s >>= 1) {
            if (tid < s) {
                sRed[tid] += sRed[tid + s];
                sRed[256 + tid] += sRed[256 + tid + s];
            }
            __syncthreads();
        }
        if (tid == 0) {
            out[OUT_COMMIT] = 0.25f * (sRed[0] / ((float)NTOK * (float)LATENT));
            out[OUT_PERP] = expf(-sRed[256]);
        }
        __syncthreads();
        for (int i = tid; i < KCODES; i += TPB) g_counts[i] = 0;
        if (tid == 0) { g_done = 0; g_ticket = 0; }
    }
}

// ---------------------------------------------------------------------------
extern "C" void kernel_launch(void* const* d_in, const int* in_sizes, int n_in,
                              void* d_out, int out_size) {
    const float* x    = (const float*)d_in[0];
    const float* ew1  = (const float*)d_in[1];
    const float* eb1  = (const float*)d_in[2];
    const float* l1g  = (const float*)d_in[3];
    const float* l1b  = (const float*)d_in[4];
    const float* ew2  = (const float*)d_in[5];
    const float* eb2  = (const float*)d_in[6];
    const float* cb   = (const float*)d_in[7];
    const float* dw1  = (const float*)d_in[8];
    const float* db1  = (const float*)d_in[9];
    const float* l2g  = (const float*)d_in[10];
    const float* l2b  = (const float*)d_in[11];
    const float* dw2  = (const float*)d_in[12];
    const float* db2  = (const float*)d_in[13];
    float* out = (float*)d_out;

    cudaFuncSetAttribute(vq_fused_kernel,
                         cudaFuncAttributeMaxDynamicSharedMemorySize, SMEM_BYTES);

    vq_prep_kernel<<<64, 512>>>(cb);
    vq_fused_kernel<<<GRID_A, TPB, SMEM_BYTES>>>(
        x, ew1, eb1, l1g, l1b, ew2, eb2, cb,
        dw1, db1, l2g, l2b, dw2, db2, out);
}